// round 1
// baseline (speedup 1.0000x reference)
#include <cuda_runtime.h>
#include <math.h>

#define BATCH   8
#define SEQL    2048
#define DMODEL  512
#define DHALF   256
#define DTYPE   32
#define DHID    (DMODEL + DTYPE)   // 544

// ---------------- scratch (no allocations allowed) ----------------
__device__ __align__(16) float g_pa[BATCH * SEQL];
__device__ __align__(16) float g_pb[BATCH * SEQL];   // pb + b_l folded
__device__ __align__(16) float g_ga[BATCH * SEQL];   // 5*ga
__device__ __align__(16) float g_gb[BATCH * SEQL];   // 5*(gb + b_g)
__device__ float g_div[DHALF];                       // div_term table

// ---------------- all-FMA transcendentals (avoid MUFU: 0.5 op/cyc/SM) ----

// exp(x) via 2^(x*log2e), magic-constant round + degree-5 poly. |rel err| ~2e-7.
__device__ __forceinline__ float fexp(float x) {
    const float L2E = 1.4426950408889634f;
    float t = fmaf(x, L2E, 12582912.0f);   // round-to-nearest int in low mantissa
    float n = t - 12582912.0f;
    float f = fmaf(x, L2E, -n);            // frac in [-0.5, 0.5]
    float p = 1.3333558e-3f;
    p = fmaf(p, f, 9.6181291e-3f);
    p = fmaf(p, f, 5.5504109e-2f);
    p = fmaf(p, f, 2.4022651e-1f);
    p = fmaf(p, f, 6.9314718e-1f);
    p = fmaf(p, f, 1.0f);
    int ib = __float_as_int(t) << 23;      // n << 23 (low bits of magic are 0)
    return __int_as_float(__float_as_int(p) + ib);
}

// ln(a) for a > 0 (njuffa-style). |rel err| ~3e-5 worst on our range.
__device__ __forceinline__ float flog(float a) {
    int e = (__float_as_int(a) - 0x3f2aaaab) & 0xff800000;
    float m = __int_as_float(__float_as_int(a) - e);   // [2/3, 4/3)
    float i = (float)e * 1.19209290e-7f;               // e * 2^-23
    float f = m - 1.0f;
    float s = f * f;
    float r = fmaf(0.230836749f, f, -0.279208571f);
    float t = fmaf(0.331826031f, f, -0.498910338f);
    r = fmaf(r, s, t);
    r = fmaf(r, s, f);
    return fmaf(i, 0.693147182f, r);
}

// 1/x via magic + 2 Newton steps. |rel err| < 2e-5.
__device__ __forceinline__ float frcp(float x) {
    float r = __int_as_float(0x7EF311C3 - __float_as_int(x));
    r = r * fmaf(-x, r, 2.0f);
    r = r * fmaf(-x, r, 2.0f);
    return r;
}

// sincos with 3-term Cody-Waite reduction, valid for |x| < ~1e4.
__device__ __forceinline__ void fsincos(float x, float& so, float& co) {
    float j = rintf(x * 0.63661977236758134f);
    float r = fmaf(j, -1.5707962512969971e+00f, x);
    r = fmaf(j, -7.5497894158615964e-08f, r);
    r = fmaf(j, -5.3903029534742384e-15f, r);
    int q = (int)j;
    float r2 = r * r;
    float sp = 2.7557319e-6f;
    sp = fmaf(sp, r2, -1.9841270e-4f);
    sp = fmaf(sp, r2, 8.3333338e-3f);
    sp = fmaf(sp, r2, -1.6666667e-1f);
    sp = fmaf(sp * r2, r, r);              // r + r^3 * poly
    float cp = 2.4801587e-5f;
    cp = fmaf(cp, r2, -1.3888889e-3f);
    cp = fmaf(cp, r2, 4.1666668e-2f);
    cp = fmaf(cp, r2, -5.0e-1f);
    cp = fmaf(cp, r2, 1.0f);
    int qm = q & 3;
    bool odd = qm & 1;
    float ss = odd ? cp : sp;
    float cc = odd ? sp : cp;
    if (qm == 2 || qm == 3) ss = -ss;
    if (qm == 1 || qm == 2) cc = -cc;
    so = ss; co = cc;
}

// ---------------- kernel 1: per-(b,l) scalars + div_term table ----------------
__global__ void scalars_kernel(const int* __restrict__ etype,
                               const float* __restrict__ temb,
                               const float* __restrict__ w_l, const float* __restrict__ b_l,
                               const float* __restrict__ w_g, const float* __restrict__ b_g) {
    int idx = blockIdx.x * blockDim.x + threadIdx.x;
    if (idx < DHALF) {
        // mirror reference: (2d as f32) * f32(-ln(1e4)/512), exp in high precision
        const float coef = (float)(-log(10000.0) / 512.0);
        float arg = (float)(2 * idx) * coef;
        g_div[idx] = (float)exp((double)arg);
    }
    if (idx >= BATCH * SEQL) return;
    int et = etype[idx];
    const float* te = temb + et * DTYPE;
    float pa = 0.f, pb = 0.f, ga = 0.f, gb = 0.f;
#pragma unroll
    for (int k = 0; k < DTYPE; k++) {
        float v = te[k];
        pa = fmaf(v, __ldg(w_l + k),         pa);
        pb = fmaf(v, __ldg(w_l + DTYPE + k), pb);
        ga = fmaf(v, __ldg(w_g + k),         ga);
        gb = fmaf(v, __ldg(w_g + DTYPE + k), gb);
    }
    g_pa[idx] = pa;
    g_pb[idx] = pb + b_l[0];
    g_ga[idx] = 5.0f * ga;
    g_gb[idx] = 5.0f * (gb + b_g[0]);
}

// ---------------- kernel 2: hidden vector [B,L,544] ----------------
__global__ void hidden_kernel(const int* __restrict__ etype,
                              const float* __restrict__ etime,
                              const float* __restrict__ Wt,
                              const float* __restrict__ temb,
                              float* __restrict__ out) {
    int row = blockIdx.x;          // b*L + l
    int l = row & (SEQL - 1);
    int d = threadIdx.x;           // 0..255
    float tval = etime[row];
    // match reference rounding: arc = pos*div (mul), phi = t*Wt (mul), then add
    float arc = __fmul_rn((float)l, g_div[d]);
    float ang = __fadd_rn(arc, __fmul_rn(tval, Wt[d]));
    float s, c;
    fsincos(ang, s, c);
    float* o = out + (size_t)row * DHID;
    o[d] = s;
    o[DHALF + d] = c;
    if (d < DTYPE) {
        int et = etype[row];
        o[DMODEL + d] = temb[et * DTYPE + d];
    }
}

// ---------------- kernel 3: pairwise scores + t_diff ----------------
__device__ __forceinline__ float score_fn(float d, float xl, float zg) {
    float l  = flog(1.0f + fexp(xl)) + 1e-6f;   // softplus + eps
    float rl = frcp(l);
    float e  = fexp(zg);
    float g  = e * frcp(1.0f + e);              // sigmoid
    float q  = d * rl;
    float kse = fexp(-0.5f * q * q);
    float kex = fexp(-q);
    return g * fmaf(0.4f, kse, 0.3f * kex);
}

__global__ void pair_kernel(const float* __restrict__ etime,
                            float* __restrict__ out_scores,
                            float* __restrict__ out_tdiff) {
    int b = blockIdx.z;
    int i = blockIdx.y;
    int j0 = (blockIdx.x * blockDim.x + threadIdx.x) * 4;

    const float* tb = etime + b * SEQL;
    float ti = tb[i];
    float4 tj = *reinterpret_cast<const float4*>(tb + j0);

    float4 td;
    td.x = fabsf(tj.x - ti);
    td.y = fabsf(tj.y - ti);
    td.z = fabsf(tj.z - ti);
    td.w = fabsf(tj.w - ti);

    size_t rowoff = ((size_t)b * SEQL + i) * SEQL + j0;
    *reinterpret_cast<float4*>(out_tdiff + rowoff) = td;

    float4 sc = make_float4(0.f, 0.f, 0.f, 0.f);
    if (j0 < i) {                                   // any kept lane in this quad
        int base = b * SEQL;
        float pbi = g_pb[base + i];
        float gbi = g_gb[base + i];
        float4 paj = *reinterpret_cast<const float4*>(g_pa + base + j0);
        float4 gaj = *reinterpret_cast<const float4*>(g_ga + base + j0);
        float s0 = score_fn(td.x, paj.x + pbi, gaj.x + gbi);
        float s1 = score_fn(td.y, paj.y + pbi, gaj.y + gbi);
        float s2 = score_fn(td.z, paj.z + pbi, gaj.z + gbi);
        float s3 = score_fn(td.w, paj.w + pbi, gaj.w + gbi);
        sc.x = s0;
        sc.y = (j0 + 1 < i) ? s1 : 0.f;
        sc.z = (j0 + 2 < i) ? s2 : 0.f;
        sc.w = (j0 + 3 < i) ? s3 : 0.f;
    }
    *reinterpret_cast<float4*>(out_scores + rowoff) = sc;
}

// ---------------- launch ----------------
extern "C" void kernel_launch(void* const* d_in, const int* in_sizes, int n_in,
                              void* d_out, int out_size) {
    const int*   etype = (const int*)d_in[0];
    const float* etime = (const float*)d_in[1];
    // d_in[2] = arrival_times (unused by reference outputs)
    const float* Wt    = (const float*)d_in[3];
    const float* temb  = (const float*)d_in[4];
    const float* w_l   = (const float*)d_in[5];
    const float* b_l   = (const float*)d_in[6];
    const float* w_g   = (const float*)d_in[7];
    const float* b_g   = (const float*)d_in[8];

    float* out        = (float*)d_out;
    float* out_scores = out;                                          // [B,L,L]
    float* out_hidden = out + (size_t)BATCH * SEQL * SEQL;            // [B,L,544]
    float* out_tdiff  = out_hidden + (size_t)BATCH * SEQL * DHID;     // [B,L,L]

    scalars_kernel<<<(BATCH * SEQL + 255) / 256, 256>>>(etype, temb, w_l, b_l, w_g, b_g);
    hidden_kernel<<<BATCH * SEQL, DHALF>>>(etype, etime, Wt, temb, out_hidden);

    dim3 grid(SEQL / (256 * 4), SEQL, BATCH);
    pair_kernel<<<grid, 256>>>(etime, out_scores, out_tdiff);
}

// round 2
// speedup vs baseline: 1.1941x; 1.1941x over previous
#include <cuda_runtime.h>
#include <math.h>

#define BATCH   8
#define SEQL    2048
#define DMODEL  512
#define DHALF   256
#define DTYPE   32
#define DHID    (DMODEL + DTYPE)   // 544

// ---------------- scratch (no allocations allowed) ----------------
__device__ __align__(16) float g_epa[BATCH * SEQL];  // exp(pa_j)
__device__ __align__(16) float g_epb[BATCH * SEQL];  // exp(pb_i + b_l)
__device__ __align__(16) float g_ega[BATCH * SEQL];  // exp(5*ga_j)
__device__ __align__(16) float g_egb[BATCH * SEQL];  // exp(5*(gb_i + b_g))
__device__ float g_div[DHALF];                       // accurate div_term table

// ---------------- MUFU intrinsics (offload from FMA pipe) ----------------
__device__ __forceinline__ float fex2(float x) {
    float r; asm("ex2.approx.f32 %0, %1;" : "=f"(r) : "f"(x)); return r;
}
__device__ __forceinline__ float flg2(float x) {
    float r; asm("lg2.approx.f32 %0, %1;" : "=f"(r) : "f"(x)); return r;
}
__device__ __forceinline__ float frcpa(float x) {
    float r; asm("rcp.approx.f32 %0, %1;" : "=f"(r) : "f"(x)); return r;
}

// exp(x) via FMA-pipe poly (used only in low-volume setup paths). rel err ~2e-7.
__device__ __forceinline__ float fexp(float x) {
    const float L2E = 1.4426950408889634f;
    float t = fmaf(x, L2E, 12582912.0f);
    float n = t - 12582912.0f;
    float f = fmaf(x, L2E, -n);
    float p = 1.3333558e-3f;
    p = fmaf(p, f, 9.6181291e-3f);
    p = fmaf(p, f, 5.5504109e-2f);
    p = fmaf(p, f, 2.4022651e-1f);
    p = fmaf(p, f, 6.9314718e-1f);
    p = fmaf(p, f, 1.0f);
    int ib = __float_as_int(t) << 23;
    return __int_as_float(__float_as_int(p) + ib);
}

// accurate sincos, 3-term Cody-Waite, valid for |x| < ~1e4.
__device__ __forceinline__ void fsincos(float x, float& so, float& co) {
    float j = rintf(x * 0.63661977236758134f);
    float r = fmaf(j, -1.5707962512969971e+00f, x);
    r = fmaf(j, -7.5497894158615964e-08f, r);
    r = fmaf(j, -5.3903029534742384e-15f, r);
    int q = (int)j;
    float r2 = r * r;
    float sp = 2.7557319e-6f;
    sp = fmaf(sp, r2, -1.9841270e-4f);
    sp = fmaf(sp, r2, 8.3333338e-3f);
    sp = fmaf(sp, r2, -1.6666667e-1f);
    sp = fmaf(sp * r2, r, r);
    float cp = 2.4801587e-5f;
    cp = fmaf(cp, r2, -1.3888889e-3f);
    cp = fmaf(cp, r2, 4.1666668e-2f);
    cp = fmaf(cp, r2, -5.0e-1f);
    cp = fmaf(cp, r2, 1.0f);
    int qm = q & 3;
    bool odd = qm & 1;
    float ss = odd ? cp : sp;
    float cc = odd ? sp : cp;
    if (qm == 2 || qm == 3) ss = -ss;
    if (qm == 1 || qm == 2) cc = -cc;
    so = ss; co = cc;
}

// ---------------- kernel 0: accurate div_term table (1 block) ----------------
__global__ void div_kernel() {
    int d = threadIdx.x;
    const float coef = (float)(-log(10000.0) / 512.0);
    float arg = (float)(2 * d) * coef;          // matches reference f32 multiply
    g_div[d] = (float)exp((double)arg);         // near-correctly-rounded
}

// ---------------- kernel 1: hidden vector + per-row exp'd scalars ----------------
__global__ void hidden_kernel(const int* __restrict__ etype,
                              const float* __restrict__ etime,
                              const float* __restrict__ Wt,
                              const float* __restrict__ temb,
                              const float* __restrict__ w_l, const float* __restrict__ b_l,
                              const float* __restrict__ w_g, const float* __restrict__ b_g,
                              float* __restrict__ out) {
    int row = blockIdx.x;          // b*L + l
    int l = row & (SEQL - 1);
    int d = threadIdx.x;           // 0..255
    float tval = __ldg(etime + row);
    int et = __ldg(etype + row);

    float arc = __fmul_rn((float)l, g_div[d]);
    float ang = __fadd_rn(arc, __fmul_rn(tval, __ldg(Wt + d)));
    float s, c;
    fsincos(ang, s, c);
    float* o = out + (size_t)row * DHID;
    o[d] = s;
    o[DHALF + d] = c;
    if (d < DTYPE) {
        o[DMODEL + d] = __ldg(temb + et * DTYPE + d);
    }

    // warp 0: four length-32 dot products -> exp'd per-row scalars
    if (d < 32) {
        float v  = __ldg(temb + et * DTYPE + d);
        float pa = v * __ldg(w_l + d);
        float pb = v * __ldg(w_l + DTYPE + d);
        float ga = v * __ldg(w_g + d);
        float gb = v * __ldg(w_g + DTYPE + d);
#pragma unroll
        for (int off = 16; off > 0; off >>= 1) {
            pa += __shfl_xor_sync(0xffffffffu, pa, off);
            pb += __shfl_xor_sync(0xffffffffu, pb, off);
            ga += __shfl_xor_sync(0xffffffffu, ga, off);
            gb += __shfl_xor_sync(0xffffffffu, gb, off);
        }
        if (d == 0) {
            g_epa[row] = fexp(pa);
            g_epb[row] = fexp(pb + __ldg(b_l));
            g_ega[row] = fexp(5.0f * ga);
            g_egb[row] = fexp(5.0f * (gb + __ldg(b_g)));
        }
    }
}

// ---------------- kernel 2: pairwise scores + t_diff ----------------
__device__ __forceinline__ float score_fn(float d, float el, float eg) {
    // softplus(pa+pb+b_l) = ln(1 + exp(pa)*exp(pb+b_l)), via MUFU lg2
    float l  = fmaf(flg2(1.0f + el), 0.69314718055994531f, 1e-6f);
    float rl = frcpa(l);
    float q  = d * rl;
    float kse = fex2(-0.72134752044448170f * q * q);   // exp(-0.5 q^2)
    float kex = fex2(-1.44269504088896340f * q);       // exp(-q)
    float g   = eg * frcpa(1.0f + eg);                 // sigmoid
    return g * fmaf(0.4f, kse, 0.3f * kex);
}

__global__ void pair_kernel(const float* __restrict__ etime,
                            float* __restrict__ out_scores,
                            float* __restrict__ out_tdiff) {
    int b = blockIdx.z;
    int i = blockIdx.y;
    int j0 = (blockIdx.x * blockDim.x + threadIdx.x) * 4;

    const float* tb = etime + b * SEQL;
    float ti = __ldg(tb + i);
    float4 tj = *reinterpret_cast<const float4*>(tb + j0);

    float4 td;
    td.x = fabsf(tj.x - ti);
    td.y = fabsf(tj.y - ti);
    td.z = fabsf(tj.z - ti);
    td.w = fabsf(tj.w - ti);

    size_t rowoff = ((size_t)b * SEQL + i) * SEQL + j0;
    *reinterpret_cast<float4*>(out_tdiff + rowoff) = td;

    float4 sc = make_float4(0.f, 0.f, 0.f, 0.f);
    if (j0 < i) {                                   // any kept lane in this quad
        int base = b * SEQL;
        float epbi = g_epb[base + i];
        float egbi = g_egb[base + i];
        float4 epaj = *reinterpret_cast<const float4*>(g_epa + base + j0);
        float4 egaj = *reinterpret_cast<const float4*>(g_ega + base + j0);
        float s0 = score_fn(td.x, epaj.x * epbi, egaj.x * egbi);
        float s1 = score_fn(td.y, epaj.y * epbi, egaj.y * egbi);
        float s2 = score_fn(td.z, epaj.z * epbi, egaj.z * egbi);
        float s3 = score_fn(td.w, epaj.w * epbi, egaj.w * egbi);
        sc.x = s0;
        sc.y = (j0 + 1 < i) ? s1 : 0.f;
        sc.z = (j0 + 2 < i) ? s2 : 0.f;
        sc.w = (j0 + 3 < i) ? s3 : 0.f;
    }
    *reinterpret_cast<float4*>(out_scores + rowoff) = sc;
}

// ---------------- launch ----------------
extern "C" void kernel_launch(void* const* d_in, const int* in_sizes, int n_in,
                              void* d_out, int out_size) {
    const int*   etype = (const int*)d_in[0];
    const float* etime = (const float*)d_in[1];
    // d_in[2] = arrival_times (unused by reference outputs)
    const float* Wt    = (const float*)d_in[3];
    const float* temb  = (const float*)d_in[4];
    const float* w_l   = (const float*)d_in[5];
    const float* b_l   = (const float*)d_in[6];
    const float* w_g   = (const float*)d_in[7];
    const float* b_g   = (const float*)d_in[8];

    float* out        = (float*)d_out;
    float* out_scores = out;                                          // [B,L,L]
    float* out_hidden = out + (size_t)BATCH * SEQL * SEQL;            // [B,L,544]
    float* out_tdiff  = out_hidden + (size_t)BATCH * SEQL * DHID;     // [B,L,L]

    div_kernel<<<1, DHALF>>>();
    hidden_kernel<<<BATCH * SEQL, DHALF>>>(etype, etime, Wt, temb,
                                           w_l, b_l, w_g, b_g, out_hidden);

    dim3 grid(SEQL / (256 * 4), SEQL, BATCH);
    pair_kernel<<<grid, 256>>>(etime, out_scores, out_tdiff);
}

// round 3
// speedup vs baseline: 1.4861x; 1.2445x over previous
#include <cuda_runtime.h>
#include <math.h>

#define BATCH   8
#define SEQL    2048
#define DMODEL  512
#define DHALF   256
#define DTYPE   32
#define DHID    (DMODEL + DTYPE)   // 544

// ---------------- scratch (no allocations allowed) ----------------
__device__ __align__(16) float g_epa[BATCH * SEQL];  // exp(pa_j)
__device__ __align__(16) float g_epb[BATCH * SEQL];  // exp(pb_i + b_l)
__device__ __align__(16) float g_ega[BATCH * SEQL];  // exp(5*ga_j)
__device__ __align__(16) float g_egb[BATCH * SEQL];  // exp(5*(gb_i + b_g))
__device__ float g_div[DHALF];                       // accurate div_term table

// ---------------- MUFU intrinsics (score path: huge accuracy slack) ------
__device__ __forceinline__ float fex2(float x) {
    float r; asm("ex2.approx.f32 %0, %1;" : "=f"(r) : "f"(x)); return r;
}
__device__ __forceinline__ float flg2(float x) {
    float r; asm("lg2.approx.f32 %0, %1;" : "=f"(r) : "f"(x)); return r;
}
__device__ __forceinline__ float frcpa(float x) {
    float r; asm("rcp.approx.f32 %0, %1;" : "=f"(r) : "f"(x)); return r;
}

// exp(x) via FMA-pipe poly (setup only). rel err ~2e-7.
__device__ __forceinline__ float fexp(float x) {
    const float L2E = 1.4426950408889634f;
    float t = fmaf(x, L2E, 12582912.0f);
    float n = t - 12582912.0f;
    float f = fmaf(x, L2E, -n);
    float p = 1.3333558e-3f;
    p = fmaf(p, f, 9.6181291e-3f);
    p = fmaf(p, f, 5.5504109e-2f);
    p = fmaf(p, f, 2.4022651e-1f);
    p = fmaf(p, f, 6.9314718e-1f);
    p = fmaf(p, f, 1.0f);
    int ib = __float_as_int(t) << 23;
    return __int_as_float(__float_as_int(p) + ib);
}

// accurate sincos, 3-term Cody-Waite, valid for |x| < ~1e4 (FMA pipe only).
__device__ __forceinline__ void fsincos(float x, float& so, float& co) {
    float j = rintf(x * 0.63661977236758134f);
    float r = fmaf(j, -1.5707962512969971e+00f, x);
    r = fmaf(j, -7.5497894158615964e-08f, r);
    r = fmaf(j, -5.3903029534742384e-15f, r);
    int q = (int)j;
    float r2 = r * r;
    float sp = 2.7557319e-6f;
    sp = fmaf(sp, r2, -1.9841270e-4f);
    sp = fmaf(sp, r2, 8.3333338e-3f);
    sp = fmaf(sp, r2, -1.6666667e-1f);
    sp = fmaf(sp * r2, r, r);
    float cp = 2.4801587e-5f;
    cp = fmaf(cp, r2, -1.3888889e-3f);
    cp = fmaf(cp, r2, 4.1666668e-2f);
    cp = fmaf(cp, r2, -5.0e-1f);
    cp = fmaf(cp, r2, 1.0f);
    int qm = q & 3;
    bool odd = qm & 1;
    float ss = odd ? cp : sp;
    float cc = odd ? sp : cp;
    if (qm == 2 || qm == 3) ss = -ss;
    if (qm == 1 || qm == 2) cc = -cc;
    so = ss; co = cc;
}

// streaming float4 store (bypass L2 retention for write-once data)
__device__ __forceinline__ void stcs4(float* p, float4 v) {
    asm volatile("st.global.cs.v4.f32 [%0], {%1,%2,%3,%4};"
                 :: "l"(p), "f"(v.x), "f"(v.y), "f"(v.z), "f"(v.w) : "memory");
}
__device__ __forceinline__ void stcs1(float* p, float v) {
    asm volatile("st.global.cs.f32 [%0], %1;" :: "l"(p), "f"(v) : "memory");
}

// ---------------- kernel 1: setup (div table + per-row exp'd scalars) ------
// grid = 2048 blocks x 256 threads; warp w of block x handles row x*8+w.
__global__ void setup_kernel(const int* __restrict__ etype,
                             const float* __restrict__ temb,
                             const float* __restrict__ w_l, const float* __restrict__ b_l,
                             const float* __restrict__ w_g, const float* __restrict__ b_g) {
    int tid = threadIdx.x;
    if (blockIdx.x == 0) {
        // accurate div_term: f32 arg (matches reference), near-correctly-rounded exp
        const float coef = (float)(-log(10000.0) / 512.0);
        float arg = (float)(2 * tid) * coef;
        g_div[tid] = (float)exp((double)arg);
    }
    int lane = tid & 31;
    int row = blockIdx.x * 8 + (tid >> 5);          // 16384 rows
    int et = __ldg(etype + row);
    float v = __ldg(temb + et * DTYPE + lane);
    float pa = v * __ldg(w_l + lane);
    float pb = v * __ldg(w_l + DTYPE + lane);
    float ga = v * __ldg(w_g + lane);
    float gb = v * __ldg(w_g + DTYPE + lane);
#pragma unroll
    for (int off = 16; off > 0; off >>= 1) {
        pa += __shfl_xor_sync(0xffffffffu, pa, off);
        pb += __shfl_xor_sync(0xffffffffu, pb, off);
        ga += __shfl_xor_sync(0xffffffffu, ga, off);
        gb += __shfl_xor_sync(0xffffffffu, gb, off);
    }
    if (lane == 0) {
        g_epa[row] = fexp(pa);
        g_epb[row] = fexp(pb + __ldg(b_l));
        g_ega[row] = fexp(5.0f * ga);
        g_egb[row] = fexp(5.0f * (gb + __ldg(b_g)));
    }
}

// ---------------- kernel 2: fused pair (scores + t_diff) + hidden ----------
__device__ __forceinline__ float score_fn(float d, float el, float eg) {
    // softplus(pa+pb+b_l) = ln(1 + exp(pa)*exp(pb+b_l)), via MUFU lg2
    float l  = fmaf(flg2(1.0f + el), 0.69314718055994531f, 1e-6f);
    float rl = frcpa(l);
    float q  = d * rl;
    float kse = fex2(-0.72134752044448170f * q * q);   // exp(-0.5 q^2)
    float kex = fex2(-1.44269504088896340f * q);       // exp(-q)
    float g   = eg * frcpa(1.0f + eg);                 // sigmoid
    return g * fmaf(0.4f, kse, 0.3f * kex);
}

__global__ void fused_kernel(const int* __restrict__ etype,
                             const float* __restrict__ etime,
                             const float* __restrict__ Wt,
                             const float* __restrict__ temb,
                             float* __restrict__ out_scores,
                             float* __restrict__ out_tdiff,
                             float* __restrict__ out_hidden) {
    int b = blockIdx.z;
    int i = blockIdx.y;
    int tid = threadIdx.x;
    int j0 = (blockIdx.x * blockDim.x + tid) * 4;

    int base = b * SEQL;
    const float* tb = etime + base;
    float ti = __ldg(tb + i);
    float4 tj = *reinterpret_cast<const float4*>(tb + j0);

    float4 td;
    td.x = fabsf(tj.x - ti);
    td.y = fabsf(tj.y - ti);
    td.z = fabsf(tj.z - ti);
    td.w = fabsf(tj.w - ti);

    size_t rowoff = ((size_t)base + i) * SEQL + j0;
    stcs4(out_tdiff + rowoff, td);

    float4 sc = make_float4(0.f, 0.f, 0.f, 0.f);
    if (j0 < i) {                                   // any kept lane in this quad
        float epbi = g_epb[base + i];
        float egbi = g_egb[base + i];
        float4 epaj = *reinterpret_cast<const float4*>(g_epa + base + j0);
        float4 egaj = *reinterpret_cast<const float4*>(g_ega + base + j0);
        float s0 = score_fn(td.x, epaj.x * epbi, egaj.x * egbi);
        float s1 = score_fn(td.y, epaj.y * epbi, egaj.y * egbi);
        float s2 = score_fn(td.z, epaj.z * epbi, egaj.z * egbi);
        float s3 = score_fn(td.w, epaj.w * epbi, egaj.w * egbi);
        sc.x = s0;
        sc.y = (j0 + 1 < i) ? s1 : 0.f;
        sc.z = (j0 + 2 < i) ? s2 : 0.f;
        sc.w = (j0 + 3 < i) ? s3 : 0.f;
    }
    stcs4(out_scores + rowoff, sc);

    // blockIdx.x==0 additionally emits hidden row (b,i): sincos + type gather.
    // Math is bit-identical to the passing round-1/2 hidden kernel.
    if (blockIdx.x == 0) {
        int row = base + i;
        float arc = __fmul_rn((float)i, g_div[tid]);
        float ang = __fadd_rn(arc, __fmul_rn(ti, __ldg(Wt + tid)));
        float s, c;
        fsincos(ang, s, c);
        float* o = out_hidden + (size_t)row * DHID;
        stcs1(o + tid, s);
        stcs1(o + DHALF + tid, c);
        if (tid < DTYPE) {
            int et = __ldg(etype + row);
            stcs1(o + DMODEL + tid, __ldg(temb + et * DTYPE + tid));
        }
    }
}

// ---------------- launch ----------------
extern "C" void kernel_launch(void* const* d_in, const int* in_sizes, int n_in,
                              void* d_out, int out_size) {
    const int*   etype = (const int*)d_in[0];
    const float* etime = (const float*)d_in[1];
    // d_in[2] = arrival_times (unused by reference outputs)
    const float* Wt    = (const float*)d_in[3];
    const float* temb  = (const float*)d_in[4];
    const float* w_l   = (const float*)d_in[5];
    const float* b_l   = (const float*)d_in[6];
    const float* w_g   = (const float*)d_in[7];
    const float* b_g   = (const float*)d_in[8];

    float* out        = (float*)d_out;
    float* out_scores = out;                                          // [B,L,L]
    float* out_hidden = out + (size_t)BATCH * SEQL * SEQL;            // [B,L,544]
    float* out_tdiff  = out_hidden + (size_t)BATCH * SEQL * DHID;     // [B,L,L]

    setup_kernel<<<SEQL, 256>>>(etype, temb, w_l, b_l, w_g, b_g);

    dim3 grid(SEQL / (256 * 4), SEQL, BATCH);
    fused_kernel<<<grid, 256>>>(etype, etime, Wt, temb,
                                out_scores, out_tdiff, out_hidden);
}